// round 2
// baseline (speedup 1.0000x reference)
#include <cuda_runtime.h>
#include <math.h>

#define B_   4
#define L_   2048
#define D_   256
#define H_   4
#define NL_  4
#define V_   32000
#define DH_  64
#define FF_  (4*D_)
#define MTOK (B_*L_)

// ---------------- scratch (allocation-free: __device__ globals) ----------------
__device__ float g_x [MTOK*D_];
__device__ float g_xn[MTOK*D_];
__device__ float g_q [MTOK*D_];
__device__ float g_k [MTOK*D_];
__device__ float g_v [MTOK*D_];
__device__ float g_at[MTOK*D_];
__device__ float g_ff[MTOK*FF_];

// ---------------- embedding ----------------
__global__ void embed_k(const int* __restrict__ ids, const int* __restrict__ tys,
                        const float* __restrict__ tok_emb, const float* __restrict__ type_emb,
                        float* __restrict__ x) {
    int i = blockIdx.x * 256 + threadIdx.x;          // over MTOK*D
    int t = i / D_, d = i - t * D_;
    x[i] = tok_emb[(size_t)ids[t] * D_ + d] + type_emb[tys[t] * D_ + d];
}

// ---------------- RMSNorm (one block per token row, 256 threads) ----------------
__global__ void rms_k(const float* __restrict__ x, const float* __restrict__ w,
                      float* __restrict__ y) {
    int row = blockIdx.x;
    int d = threadIdx.x;
    float v = x[(size_t)row * D_ + d];
    float s = v * v;
    __shared__ float sh[8];
    #pragma unroll
    for (int o = 16; o; o >>= 1) s += __shfl_xor_sync(0xFFFFFFFFu, s, o);
    if ((threadIdx.x & 31) == 0) sh[threadIdx.x >> 5] = s;
    __syncthreads();
    if (threadIdx.x < 8) {
        float t = sh[threadIdx.x];
        #pragma unroll
        for (int o = 4; o; o >>= 1) t += __shfl_xor_sync(0xFFu, t, o);
        if (threadIdx.x == 0) sh[0] = t;
    }
    __syncthreads();
    float mean = sh[0] * (1.0f / D_);
    float r = rsqrtf(mean + 1.1920929e-07f);         // finfo(float32).eps
    y[(size_t)row * D_ + d] = v * r * w[d];
}

// ---------------- RoPE in-place on q and k ----------------
__global__ void rope_k(float* __restrict__ q, float* __restrict__ k) {
    int i = blockIdx.x * 256 + threadIdx.x;          // over MTOK*H*32
    int j  = i & 31;                                  // freq index
    int hh = (i >> 5) & (H_ - 1);
    int t  = i >> 7;                                  // token index (H*32 = 128)
    int pos = t & (L_ - 1);
    float freq = expf(-logf(10000.0f) * (float)j * (1.0f / 32.0f));
    float ang = (float)pos * freq;
    float c = cosf(ang), s = sinf(ang);
    size_t base = (size_t)t * D_ + hh * DH_ + j;
    float q0 = q[base], q1 = q[base + 32];
    q[base]      = q0 * c - q1 * s;
    q[base + 32] = q1 * c + q0 * s;
    float k0 = k[base], k1 = k[base + 32];
    k[base]      = k0 * c - k1 * s;
    k[base + 32] = k1 * c + k0 * s;
}

// ---------------- flash-style causal attention ----------------
// grid (L/128, H, B), 128 threads; thread = one query row; streaming softmax.
__global__ void __launch_bounds__(128) attn_k(const float* __restrict__ q,
                                              const float* __restrict__ k,
                                              const float* __restrict__ v,
                                              const int* __restrict__ am,
                                              float* __restrict__ out) {
    int qt = blockIdx.x, h = blockIdx.y, b = blockIdx.z;
    int qrow = qt * 128 + threadIdx.x;
    __shared__ float Ks[64][64];
    __shared__ float Vs[64][64];
    __shared__ int   Ms[64];

    float qr[64];
    size_t qbase = ((size_t)(b * L_ + qrow)) * D_ + h * DH_;
    #pragma unroll
    for (int d = 0; d < 64; d++) qr[d] = q[qbase + d] * 0.125f;   // fold DH^-0.5

    float m = -1e30f, l = 0.0f;
    float acc[64];
    #pragma unroll
    for (int d = 0; d < 64; d++) acc[d] = 0.0f;

    int ntiles = 2 * qt + 2;                       // keys 0 .. qt*128+127
    for (int kt = 0; kt < ntiles; kt++) {
        int krow0 = kt * 64;
        {   // cooperative tile load: 128 threads, each half-row (32 floats) of K and V
            int r = threadIdx.x >> 1, half = (threadIdx.x & 1) * 32;
            size_t gb = ((size_t)(b * L_ + krow0 + r)) * D_ + h * DH_ + half;
            float4*       Kd = (float4*)&Ks[r][half];
            const float4* Kg = (const float4*)(k + gb);
            float4*       Vd = (float4*)&Vs[r][half];
            const float4* Vg = (const float4*)(v + gb);
            #pragma unroll
            for (int u = 0; u < 8; u++) { Kd[u] = Kg[u]; Vd[u] = Vg[u]; }
            if (threadIdx.x < 64) Ms[threadIdx.x] = am[b * L_ + krow0 + threadIdx.x];
        }
        __syncthreads();
        int klim = qrow - krow0 + 1;
        if (klim > 64) klim = 64;
        for (int kk = 0; kk < klim; kk++) {
            if (Ms[kk]) {
                float s = 0.0f;
                #pragma unroll
                for (int d = 0; d < 64; d++) s += qr[d] * Ks[kk][d];
                if (s > m) {
                    float c0 = expf(m - s);
                    l *= c0;
                    #pragma unroll
                    for (int d = 0; d < 64; d++) acc[d] *= c0;
                    m = s;
                }
                float p = expf(s - m);
                l += p;
                #pragma unroll
                for (int d = 0; d < 64; d++) acc[d] += p * Vs[kk][d];
            }
        }
        __syncthreads();
    }
    float inv = (l > 0.0f) ? (1.0f / l) : 0.0f;
    #pragma unroll
    for (int d = 0; d < 64; d++) out[qbase + d] = acc[d] * inv;
}

// ---------------- tiled fp32 GEMM: C[m,n] = sum_k A[m,k] * W[n,k] (+epilogue) ----------------
// EPI: 0 = plain, 1 = residual add (C = R + AB), 2 = SiLU(AB)
// 64x64 tile, BK=16, 256 threads, 4x4 per thread. M%64==0, N%64==0, K%16==0.
template <int EPI>
__global__ void __launch_bounds__(256) gemm_atw(const float* __restrict__ A,
                                                const float* __restrict__ W,
                                                const float* __restrict__ R,
                                                float* __restrict__ C,
                                                int M, int N, int K) {
    __shared__ float As[16][64];
    __shared__ float Ws[16][64];
    int bm = blockIdx.y * 64, bn = blockIdx.x * 64;
    int tid = threadIdx.x;
    int tx = tid & 15, ty = tid >> 4;
    int lrow = tid >> 2;
    int lk   = (tid & 3) << 2;
    const float* Ap = A + (size_t)(bm + lrow) * K + lk;
    const float* Wp = W + (size_t)(bn + lrow) * K + lk;
    float acc[4][4] = {};
    for (int k0 = 0; k0 < K; k0 += 16) {
        float4 a = *(const float4*)(Ap + k0);
        float4 w = *(const float4*)(Wp + k0);
        As[lk + 0][lrow] = a.x; As[lk + 1][lrow] = a.y;
        As[lk + 2][lrow] = a.z; As[lk + 3][lrow] = a.w;
        Ws[lk + 0][lrow] = w.x; Ws[lk + 1][lrow] = w.y;
        Ws[lk + 2][lrow] = w.z; Ws[lk + 3][lrow] = w.w;
        __syncthreads();
        #pragma unroll
        for (int kk = 0; kk < 16; kk++) {
            float4 av = *(const float4*)&As[kk][ty << 2];
            float4 wv = *(const float4*)&Ws[kk][tx << 2];
            float ar[4] = {av.x, av.y, av.z, av.w};
            float wr[4] = {wv.x, wv.y, wv.z, wv.w};
            #pragma unroll
            for (int i = 0; i < 4; i++)
                #pragma unroll
                for (int j = 0; j < 4; j++) acc[i][j] += ar[i] * wr[j];
        }
        __syncthreads();
    }
    #pragma unroll
    for (int i = 0; i < 4; i++) {
        size_t idx = (size_t)(bm + (ty << 2) + i) * N + bn + (tx << 2);
        float4 vv = make_float4(acc[i][0], acc[i][1], acc[i][2], acc[i][3]);
        if (EPI == 1) {
            float4 rr = *(const float4*)(R + idx);
            vv.x += rr.x; vv.y += rr.y; vv.z += rr.z; vv.w += rr.w;
        }
        if (EPI == 2) {
            vv.x = vv.x / (1.0f + expf(-vv.x));
            vv.y = vv.y / (1.0f + expf(-vv.y));
            vv.z = vv.z / (1.0f + expf(-vv.z));
            vv.w = vv.w / (1.0f + expf(-vv.w));
        }
        *(float4*)(C + idx) = vv;
    }
}

// ---------------- classifier heads on cls token (b, 0) ----------------
__global__ void heads_k(const float* __restrict__ xn,
                        const float* __restrict__ rw, const float* __restrict__ rb,
                        const float* __restrict__ mw, const float* __restrict__ mb,
                        float* __restrict__ out) {
    int b = blockIdx.x;
    int t = threadIdx.x;                              // 256 = D
    float xv = xn[((size_t)b * L_) * D_ + t];
    float pr = xv * rw[t];
    float pm = xv * mw[t];
    __shared__ float sr[8], sm_[8];
    #pragma unroll
    for (int o = 16; o; o >>= 1) {
        pr += __shfl_xor_sync(0xFFFFFFFFu, pr, o);
        pm += __shfl_xor_sync(0xFFFFFFFFu, pm, o);
    }
    if ((t & 31) == 0) { sr[t >> 5] = pr; sm_[t >> 5] = pm; }
    __syncthreads();
    if (t == 0) {
        float a = 0.0f, c = 0.0f;
        #pragma unroll
        for (int i = 0; i < 8; i++) { a += sr[i]; c += sm_[i]; }
        out[b]      = a + rb[0];
        out[B_ + b] = c + mb[0];
    }
}

// ---------------- driver ----------------
extern "C" void kernel_launch(void* const* d_in, const int* in_sizes, int n_in,
                              void* d_out, int out_size) {
    const int*   token_ids    = (const int*)  d_in[0];
    const int*   token_types  = (const int*)  d_in[1];
    const int*   amask        = (const int*)  d_in[2];
    const float* tok_emb      = (const float*)d_in[3];
    const float* type_emb     = (const float*)d_in[4];
    const float* norm1_w      = (const float*)d_in[5];
    const float* wq           = (const float*)d_in[6];
    const float* wk           = (const float*)d_in[7];
    const float* wv           = (const float*)d_in[8];
    const float* wo           = (const float*)d_in[9];
    const float* norm2_w      = (const float*)d_in[10];
    const float* ff_w1        = (const float*)d_in[11];
    const float* ff_w2        = (const float*)d_in[12];
    const float* final_norm_w = (const float*)d_in[13];
    const float* lm_w         = (const float*)d_in[14];
    const float* read_w       = (const float*)d_in[15];
    const float* read_b       = (const float*)d_in[16];
    const float* mort_w       = (const float*)d_in[17];
    const float* mort_b       = (const float*)d_in[18];
    float* out = (float*)d_out;

    float *x, *xn, *q, *k, *v, *at, *ff;
    cudaGetSymbolAddress((void**)&x,  g_x);
    cudaGetSymbolAddress((void**)&xn, g_xn);
    cudaGetSymbolAddress((void**)&q,  g_q);
    cudaGetSymbolAddress((void**)&k,  g_k);
    cudaGetSymbolAddress((void**)&v,  g_v);
    cudaGetSymbolAddress((void**)&at, g_at);
    cudaGetSymbolAddress((void**)&ff, g_ff);

    embed_k<<<MTOK * D_ / 256, 256>>>(token_ids, token_types, tok_emb, type_emb, x);

    dim3 gqkv(D_ / 64, MTOK / 64);
    dim3 gff1(FF_ / 64, MTOK / 64);
    for (int li = 0; li < NL_; li++) {
        rms_k<<<MTOK, 256>>>(x, norm1_w + li * D_, xn);
        gemm_atw<0><<<gqkv, 256>>>(xn, wq + (size_t)li * D_ * D_, nullptr, q, MTOK, D_, D_);
        gemm_atw<0><<<gqkv, 256>>>(xn, wk + (size_t)li * D_ * D_, nullptr, k, MTOK, D_, D_);
        gemm_atw<0><<<gqkv, 256>>>(xn, wv + (size_t)li * D_ * D_, nullptr, v, MTOK, D_, D_);
        rope_k<<<MTOK * H_ * 32 / 256, 256>>>(q, k);
        attn_k<<<dim3(L_ / 128, H_, B_), 128>>>(q, k, v, amask, at);
        gemm_atw<1><<<gqkv, 256>>>(at, wo + (size_t)li * D_ * D_, x, x, MTOK, D_, D_);
        rms_k<<<MTOK, 256>>>(x, norm2_w + li * D_, xn);
        gemm_atw<2><<<gff1, 256>>>(xn, ff_w1 + (size_t)li * FF_ * D_, nullptr, ff, MTOK, FF_, D_);
        gemm_atw<1><<<gqkv, 256>>>(ff, ff_w2 + (size_t)li * D_ * FF_, x, x, MTOK, D_, FF_);
    }
    rms_k<<<MTOK, 256>>>(x, final_norm_w, xn);
    gemm_atw<0><<<dim3(V_ / 64, MTOK / 64), 256>>>(xn, lm_w, nullptr, out, MTOK, V_, D_);
    heads_k<<<B_, 256>>>(xn, read_w, read_b, mort_w, mort_b, out + (size_t)MTOK * V_);
}

// round 3
// speedup vs baseline: 1.2416x; 1.2416x over previous
#include <cuda_runtime.h>
#include <math.h>

#define B_   4
#define L_   2048
#define D_   256
#define H_   4
#define NL_  4
#define V_   32000
#define DH_  64
#define FF_  (4*D_)
#define MTOK (B_*L_)

// ---------------- scratch (allocation-free: __device__ globals) ----------------
__device__ float g_x [MTOK*D_];
__device__ float g_xn[MTOK*D_];
__device__ float g_q [MTOK*D_];
__device__ float g_k [MTOK*D_];
__device__ float g_v [MTOK*D_];
__device__ float g_at[MTOK*D_];
__device__ float g_ff[MTOK*FF_];

// ---------------- embedding ----------------
__global__ void embed_k(const int* __restrict__ ids, const int* __restrict__ tys,
                        const float* __restrict__ tok_emb, const float* __restrict__ type_emb,
                        float* __restrict__ x) {
    int i = blockIdx.x * 256 + threadIdx.x;          // over MTOK*D
    int t = i / D_, d = i - t * D_;
    x[i] = tok_emb[(size_t)ids[t] * D_ + d] + type_emb[tys[t] * D_ + d];
}

// ---------------- RMSNorm (one block per token row, 256 threads) ----------------
__global__ void rms_k(const float* __restrict__ x, const float* __restrict__ w,
                      float* __restrict__ y) {
    int row = blockIdx.x;
    int d = threadIdx.x;
    float v = x[(size_t)row * D_ + d];
    float s = v * v;
    __shared__ float sh[8];
    #pragma unroll
    for (int o = 16; o; o >>= 1) s += __shfl_xor_sync(0xFFFFFFFFu, s, o);
    if ((threadIdx.x & 31) == 0) sh[threadIdx.x >> 5] = s;
    __syncthreads();
    if (threadIdx.x < 8) {
        float t = sh[threadIdx.x];
        #pragma unroll
        for (int o = 4; o; o >>= 1) t += __shfl_xor_sync(0xFFu, t, o);
        if (threadIdx.x == 0) sh[0] = t;
    }
    __syncthreads();
    float mean = sh[0] * (1.0f / D_);
    float r = rsqrtf(mean + 1.1920929e-07f);         // finfo(float32).eps
    y[(size_t)row * D_ + d] = v * r * w[d];
}

// ---------------- RoPE in-place on q and k ----------------
__global__ void rope_k(float* __restrict__ q, float* __restrict__ k) {
    int i = blockIdx.x * 256 + threadIdx.x;          // over MTOK*H*32
    int j  = i & 31;                                  // freq index
    int hh = (i >> 5) & (H_ - 1);
    int t  = i >> 7;                                  // token index (H*32 = 128)
    int pos = t & (L_ - 1);
    float freq = expf(-logf(10000.0f) * (float)j * (1.0f / 32.0f));
    float ang = (float)pos * freq;
    float c = cosf(ang), s = sinf(ang);
    size_t base = (size_t)t * D_ + hh * DH_ + j;
    float q0 = q[base], q1 = q[base + 32];
    q[base]      = q0 * c - q1 * s;
    q[base + 32] = q1 * c + q0 * s;
    float k0 = k[base], k1 = k[base + 32];
    k[base]      = k0 * c - k1 * s;
    k[base + 32] = k1 * c + k0 * s;
}

// ---------------- flash-style causal attention ----------------
__global__ void __launch_bounds__(128) attn_k(const float* __restrict__ q,
                                              const float* __restrict__ k,
                                              const float* __restrict__ v,
                                              const int* __restrict__ am,
                                              float* __restrict__ out) {
    int qt = blockIdx.x, h = blockIdx.y, b = blockIdx.z;
    int qrow = qt * 128 + threadIdx.x;
    __shared__ float Ks[64][64];
    __shared__ float Vs[64][64];
    __shared__ int   Ms[64];

    float qr[64];
    size_t qbase = ((size_t)(b * L_ + qrow)) * D_ + h * DH_;
    #pragma unroll
    for (int d = 0; d < 64; d++) qr[d] = q[qbase + d] * 0.125f;

    float m = -1e30f, l = 0.0f;
    float acc[64];
    #pragma unroll
    for (int d = 0; d < 64; d++) acc[d] = 0.0f;

    int ntiles = 2 * qt + 2;
    for (int kt = 0; kt < ntiles; kt++) {
        int krow0 = kt * 64;
        {
            int r = threadIdx.x >> 1, half = (threadIdx.x & 1) * 32;
            size_t gb = ((size_t)(b * L_ + krow0 + r)) * D_ + h * DH_ + half;
            float4*       Kd = (float4*)&Ks[r][half];
            const float4* Kg = (const float4*)(k + gb);
            float4*       Vd = (float4*)&Vs[r][half];
            const float4* Vg = (const float4*)(v + gb);
            #pragma unroll
            for (int u = 0; u < 8; u++) { Kd[u] = Kg[u]; Vd[u] = Vg[u]; }
            if (threadIdx.x < 64) Ms[threadIdx.x] = am[b * L_ + krow0 + threadIdx.x];
        }
        __syncthreads();
        int klim = qrow - krow0 + 1;
        if (klim > 64) klim = 64;
        for (int kk = 0; kk < klim; kk++) {
            if (Ms[kk]) {
                float s = 0.0f;
                #pragma unroll
                for (int d = 0; d < 64; d++) s += qr[d] * Ks[kk][d];
                if (s > m) {
                    float c0 = expf(m - s);
                    l *= c0;
                    #pragma unroll
                    for (int d = 0; d < 64; d++) acc[d] *= c0;
                    m = s;
                }
                float p = expf(s - m);
                l += p;
                #pragma unroll
                for (int d = 0; d < 64; d++) acc[d] += p * Vs[kk][d];
            }
        }
        __syncthreads();
    }
    float inv = (l > 0.0f) ? (1.0f / l) : 0.0f;
    #pragma unroll
    for (int d = 0; d < 64; d++) out[qbase + d] = acc[d] * inv;
}

// ---------------- tiled fp32 GEMM (layer path, exact) ----------------
template <int EPI>
__global__ void __launch_bounds__(256) gemm_atw(const float* __restrict__ A,
                                                const float* __restrict__ W,
                                                const float* __restrict__ R,
                                                float* __restrict__ C,
                                                int M, int N, int K) {
    __shared__ float As[16][64];
    __shared__ float Ws[16][64];
    int bm = blockIdx.y * 64, bn = blockIdx.x * 64;
    int tid = threadIdx.x;
    int tx = tid & 15, ty = tid >> 4;
    int lrow = tid >> 2;
    int lk   = (tid & 3) << 2;
    const float* Ap = A + (size_t)(bm + lrow) * K + lk;
    const float* Wp = W + (size_t)(bn + lrow) * K + lk;
    float acc[4][4] = {};
    for (int k0 = 0; k0 < K; k0 += 16) {
        float4 a = *(const float4*)(Ap + k0);
        float4 w = *(const float4*)(Wp + k0);
        As[lk + 0][lrow] = a.x; As[lk + 1][lrow] = a.y;
        As[lk + 2][lrow] = a.z; As[lk + 3][lrow] = a.w;
        Ws[lk + 0][lrow] = w.x; Ws[lk + 1][lrow] = w.y;
        Ws[lk + 2][lrow] = w.z; Ws[lk + 3][lrow] = w.w;
        __syncthreads();
        #pragma unroll
        for (int kk = 0; kk < 16; kk++) {
            float4 av = *(const float4*)&As[kk][ty << 2];
            float4 wv = *(const float4*)&Ws[kk][tx << 2];
            float ar[4] = {av.x, av.y, av.z, av.w};
            float wr[4] = {wv.x, wv.y, wv.z, wv.w};
            #pragma unroll
            for (int i = 0; i < 4; i++)
                #pragma unroll
                for (int j = 0; j < 4; j++) acc[i][j] += ar[i] * wr[j];
        }
        __syncthreads();
    }
    #pragma unroll
    for (int i = 0; i < 4; i++) {
        size_t idx = (size_t)(bm + (ty << 2) + i) * N + bn + (tx << 2);
        float4 vv = make_float4(acc[i][0], acc[i][1], acc[i][2], acc[i][3]);
        if (EPI == 1) {
            float4 rr = *(const float4*)(R + idx);
            vv.x += rr.x; vv.y += rr.y; vv.z += rr.z; vv.w += rr.w;
        }
        if (EPI == 2) {
            vv.x = vv.x / (1.0f + expf(-vv.x));
            vv.y = vv.y / (1.0f + expf(-vv.y));
            vv.z = vv.z / (1.0f + expf(-vv.z));
            vv.w = vv.w / (1.0f + expf(-vv.w));
        }
        *(float4*)(C + idx) = vv;
    }
}

// ---------------- tf32 tensor-core GEMM for the LM head ----------------
// C[m,n] = sum_k A[m,k] * W[n,k].  128x128x32 tiles, 8 warps (2x4), warp tile
// 64x32 via m16n8k8 tf32 MMA. Smem holds tf32-rounded values in a pair-
// interleaved layout: within each 8-wide k-group, (k, k+4) are adjacent so a
// fragment (a0,a2)/(b0,b1) is one LDS.64.  XOR swizzle (row&3)<<3 keeps the
// 64-bit fragment loads bank-conflict-free.
__device__ __forceinline__ unsigned f2tf32(float v) {
    unsigned o;
    asm("cvt.rna.tf32.f32 %0, %1;" : "=r"(o) : "f"(v));
    return o;
}
__device__ __forceinline__ int kperm(int kl) {   // kl in [0,32)
    return (kl & ~7) | ((kl & 3) << 1) | ((kl & 4) >> 2);
}
__device__ __forceinline__ int swz(int row, int col) {
    return row * 32 + (col ^ ((row & 3) << 3));
}

__global__ void __launch_bounds__(256) lm_gemm_tf32(const float* __restrict__ A,
                                                    const float* __restrict__ W,
                                                    float* __restrict__ C,
                                                    int M, int N, int K) {
    __shared__ unsigned As[128 * 32];
    __shared__ unsigned Ws[128 * 32];
    const int bm = blockIdx.y * 128, bn = blockIdx.x * 128;
    const int tid = threadIdx.x;
    const int warp = tid >> 5, lane = tid & 31;
    const int wm = warp >> 2, wn = warp & 3;          // warp grid 2x4
    const int gid = lane >> 2, qid = lane & 3;        // fragment group/thread

    // copy assignment: thread -> (row, 16-float half-row)
    const int crow = tid >> 1;
    const int ccol = (tid & 1) * 16;
    const float* Ap = A + (size_t)(bm + crow) * K + ccol;
    const float* Wp = W + (size_t)(bn + crow) * K + ccol;

    float cacc[4][4][4];                               // [mt][nt][frag]
    #pragma unroll
    for (int i = 0; i < 4; i++)
        #pragma unroll
        for (int j = 0; j < 4; j++)
            #pragma unroll
            for (int f = 0; f < 4; f++) cacc[i][j][f] = 0.0f;

    float4 pa[4], pw[4];
    #pragma unroll
    for (int u = 0; u < 4; u++) {
        pa[u] = *(const float4*)(Ap + 4 * u);
        pw[u] = *(const float4*)(Wp + 4 * u);
    }

    const int nchunks = K >> 5;                        // K/32
    for (int ch = 0; ch < nchunks; ch++) {
        // stage prefetched regs -> smem (tf32 round + permute + swizzle)
        #pragma unroll
        for (int u = 0; u < 4; u++) {
            float av[4] = {pa[u].x, pa[u].y, pa[u].z, pa[u].w};
            float wv[4] = {pw[u].x, pw[u].y, pw[u].z, pw[u].w};
            #pragma unroll
            for (int j = 0; j < 4; j++) {
                int kl = ccol + 4 * u + j;
                int c  = kperm(kl);
                As[swz(crow, c)] = f2tf32(av[j]);
                Ws[swz(crow, c)] = f2tf32(wv[j]);
            }
        }
        __syncthreads();
        if (ch + 1 < nchunks) {
            #pragma unroll
            for (int u = 0; u < 4; u++) {
                pa[u] = *(const float4*)(Ap + (ch + 1) * 32 + 4 * u);
                pw[u] = *(const float4*)(Wp + (ch + 1) * 32 + 4 * u);
            }
        }
        #pragma unroll
        for (int ks = 0; ks < 4; ks++) {
            const int c0 = ks * 8 + 2 * qid;          // pair base (k=q, k=q+4)
            unsigned afr[4][4];                        // [mt][a0,a1,a2,a3]
            unsigned bfr[4][2];                        // [nt][b0,b1]
            #pragma unroll
            for (int mt = 0; mt < 4; mt++) {
                int r0 = wm * 64 + mt * 16 + gid;
                uint2 lo = *(const uint2*)&As[swz(r0, c0)];
                uint2 hi = *(const uint2*)&As[swz(r0 + 8, c0)];
                afr[mt][0] = lo.x; afr[mt][2] = lo.y;
                afr[mt][1] = hi.x; afr[mt][3] = hi.y;
            }
            #pragma unroll
            for (int nt = 0; nt < 4; nt++) {
                int rn = wn * 32 + nt * 8 + gid;
                uint2 bb = *(const uint2*)&Ws[swz(rn, c0)];
                bfr[nt][0] = bb.x; bfr[nt][1] = bb.y;
            }
            #pragma unroll
            for (int mt = 0; mt < 4; mt++)
                #pragma unroll
                for (int nt = 0; nt < 4; nt++) {
                    asm volatile(
                        "mma.sync.aligned.m16n8k8.row.col.f32.tf32.tf32.f32 "
                        "{%0,%1,%2,%3}, {%4,%5,%6,%7}, {%8,%9}, {%0,%1,%2,%3};\n"
                        : "+f"(cacc[mt][nt][0]), "+f"(cacc[mt][nt][1]),
                          "+f"(cacc[mt][nt][2]), "+f"(cacc[mt][nt][3])
                        : "r"(afr[mt][0]), "r"(afr[mt][1]),
                          "r"(afr[mt][2]), "r"(afr[mt][3]),
                          "r"(bfr[nt][0]), "r"(bfr[nt][1]));
                }
        }
        __syncthreads();
    }

    // epilogue: c0,c1 at (row, col..col+1); c2,c3 at (row+8, col..col+1)
    #pragma unroll
    for (int mt = 0; mt < 4; mt++) {
        int row = bm + wm * 64 + mt * 16 + gid;
        #pragma unroll
        for (int nt = 0; nt < 4; nt++) {
            int col = bn + wn * 32 + nt * 8 + qid * 2;
            *(float2*)(C + (size_t)row * N + col) =
                make_float2(cacc[mt][nt][0], cacc[mt][nt][1]);
            *(float2*)(C + (size_t)(row + 8) * N + col) =
                make_float2(cacc[mt][nt][2], cacc[mt][nt][3]);
        }
    }
}

// ---------------- classifier heads on cls token (b, 0) ----------------
__global__ void heads_k(const float* __restrict__ xn,
                        const float* __restrict__ rw, const float* __restrict__ rb,
                        const float* __restrict__ mw, const float* __restrict__ mb,
                        float* __restrict__ out) {
    int b = blockIdx.x;
    int t = threadIdx.x;
    float xv = xn[((size_t)b * L_) * D_ + t];
    float pr = xv * rw[t];
    float pm = xv * mw[t];
    __shared__ float sr[8], sm_[8];
    #pragma unroll
    for (int o = 16; o; o >>= 1) {
        pr += __shfl_xor_sync(0xFFFFFFFFu, pr, o);
        pm += __shfl_xor_sync(0xFFFFFFFFu, pm, o);
    }
    if ((t & 31) == 0) { sr[t >> 5] = pr; sm_[t >> 5] = pm; }
    __syncthreads();
    if (t == 0) {
        float a = 0.0f, c = 0.0f;
        #pragma unroll
        for (int i = 0; i < 8; i++) { a += sr[i]; c += sm_[i]; }
        out[b]      = a + rb[0];
        out[B_ + b] = c + mb[0];
    }
}

// ---------------- driver ----------------
extern "C" void kernel_launch(void* const* d_in, const int* in_sizes, int n_in,
                              void* d_out, int out_size) {
    const int*   token_ids    = (const int*)  d_in[0];
    const int*   token_types  = (const int*)  d_in[1];
    const int*   amask        = (const int*)  d_in[2];
    const float* tok_emb      = (const float*)d_in[3];
    const float* type_emb     = (const float*)d_in[4];
    const float* norm1_w      = (const float*)d_in[5];
    const float* wq           = (const float*)d_in[6];
    const float* wk           = (const float*)d_in[7];
    const float* wv           = (const float*)d_in[8];
    const float* wo           = (const float*)d_in[9];
    const float* norm2_w      = (const float*)d_in[10];
    const float* ff_w1        = (const float*)d_in[11];
    const float* ff_w2        = (const float*)d_in[12];
    const float* final_norm_w = (const float*)d_in[13];
    const float* lm_w         = (const float*)d_in[14];
    const float* read_w       = (const float*)d_in[15];
    const float* read_b       = (const float*)d_in[16];
    const float* mort_w       = (const float*)d_in[17];
    const float* mort_b       = (const float*)d_in[18];
    float* out = (float*)d_out;

    float *x, *xn, *q, *k, *v, *at, *ff;
    cudaGetSymbolAddress((void**)&x,  g_x);
    cudaGetSymbolAddress((void**)&xn, g_xn);
    cudaGetSymbolAddress((void**)&q,  g_q);
    cudaGetSymbolAddress((void**)&k,  g_k);
    cudaGetSymbolAddress((void**)&v,  g_v);
    cudaGetSymbolAddress((void**)&at, g_at);
    cudaGetSymbolAddress((void**)&ff, g_ff);

    embed_k<<<MTOK * D_ / 256, 256>>>(token_ids, token_types, tok_emb, type_emb, x);

    dim3 gqkv(D_ / 64, MTOK / 64);
    dim3 gff1(FF_ / 64, MTOK / 64);
    for (int li = 0; li < NL_; li++) {
        rms_k<<<MTOK, 256>>>(x, norm1_w + li * D_, xn);
        gemm_atw<0><<<gqkv, 256>>>(xn, wq + (size_t)li * D_ * D_, nullptr, q, MTOK, D_, D_);
        gemm_atw<0><<<gqkv, 256>>>(xn, wk + (size_t)li * D_ * D_, nullptr, k, MTOK, D_, D_);
        gemm_atw<0><<<gqkv, 256>>>(xn, wv + (size_t)li * D_ * D_, nullptr, v, MTOK, D_, D_);
        rope_k<<<MTOK * H_ * 32 / 256, 256>>>(q, k);
        attn_k<<<dim3(L_ / 128, H_, B_), 128>>>(q, k, v, amask, at);
        gemm_atw<1><<<gqkv, 256>>>(at, wo + (size_t)li * D_ * D_, x, x, MTOK, D_, D_);
        rms_k<<<MTOK, 256>>>(x, norm2_w + li * D_, xn);
        gemm_atw<2><<<gff1, 256>>>(xn, ff_w1 + (size_t)li * FF_ * D_, nullptr, ff, MTOK, FF_, D_);
        gemm_atw<1><<<gqkv, 256>>>(ff, ff_w2 + (size_t)li * D_ * FF_, x, x, MTOK, D_, FF_);
    }
    rms_k<<<MTOK, 256>>>(x, final_norm_w, xn);
    lm_gemm_tf32<<<dim3(V_ / 128, MTOK / 128), 256>>>(xn, lm_w, out, MTOK, V_, D_);
    heads_k<<<B_, 256>>>(xn, read_w, read_b, mort_w, mort_b, out + (size_t)MTOK * V_);
}

// round 6
// speedup vs baseline: 1.4050x; 1.1316x over previous
#include <cuda_runtime.h>
#include <math.h>
#include <stdint.h>

#define B_   4
#define L_   2048
#define D_   256
#define H_   4
#define NL_  4
#define V_   32000
#define DH_  64
#define FF_  (4*D_)
#define MTOK (B_*L_)

// ---------------- scratch (allocation-free: __device__ globals) ----------------
__device__ float g_x [MTOK*D_];
__device__ float g_xn[MTOK*D_];
__device__ float g_q [MTOK*D_];
__device__ float g_k [MTOK*D_];
__device__ float g_v [MTOK*D_];
__device__ float g_at[MTOK*D_];
__device__ float g_ff[MTOK*FF_];
__device__ unsigned g_a32[MTOK*D_];              // tf32, k-permuted
__device__ unsigned g_w32[(size_t)V_*D_];        // tf32, k-permuted

// ---------------- embedding ----------------
__global__ void embed_k(const int* __restrict__ ids, const int* __restrict__ tys,
                        const float* __restrict__ tok_emb, const float* __restrict__ type_emb,
                        float* __restrict__ x) {
    int i = blockIdx.x * 256 + threadIdx.x;
    int t = i / D_, d = i - t * D_;
    x[i] = tok_emb[(size_t)ids[t] * D_ + d] + type_emb[tys[t] * D_ + d];
}

// ---------------- RMSNorm ----------------
__global__ void rms_k(const float* __restrict__ x, const float* __restrict__ w,
                      float* __restrict__ y) {
    int row = blockIdx.x;
    int d = threadIdx.x;
    float v = x[(size_t)row * D_ + d];
    float s = v * v;
    __shared__ float sh[8];
    #pragma unroll
    for (int o = 16; o; o >>= 1) s += __shfl_xor_sync(0xFFFFFFFFu, s, o);
    if ((threadIdx.x & 31) == 0) sh[threadIdx.x >> 5] = s;
    __syncthreads();
    if (threadIdx.x < 8) {
        float t = sh[threadIdx.x];
        #pragma unroll
        for (int o = 4; o; o >>= 1) t += __shfl_xor_sync(0xFFu, t, o);
        if (threadIdx.x == 0) sh[0] = t;
    }
    __syncthreads();
    float mean = sh[0] * (1.0f / D_);
    float r = rsqrtf(mean + 1.1920929e-07f);
    y[(size_t)row * D_ + d] = v * r * w[d];
}

// ---------------- RoPE ----------------
__global__ void rope_k(float* __restrict__ q, float* __restrict__ k) {
    int i = blockIdx.x * 256 + threadIdx.x;
    int j  = i & 31;
    int hh = (i >> 5) & (H_ - 1);
    int t  = i >> 7;
    int pos = t & (L_ - 1);
    float freq = expf(-logf(10000.0f) * (float)j * (1.0f / 32.0f));
    float ang = (float)pos * freq;
    float c = cosf(ang), s = sinf(ang);
    size_t base = (size_t)t * D_ + hh * DH_ + j;
    float q0 = q[base], q1 = q[base + 32];
    q[base]      = q0 * c - q1 * s;
    q[base + 32] = q1 * c + q0 * s;
    float k0 = k[base], k1 = k[base + 32];
    k[base]      = k0 * c - k1 * s;
    k[base + 32] = k1 * c + k0 * s;
}

// ---------------- flash-style causal attention ----------------
__global__ void __launch_bounds__(128) attn_k(const float* __restrict__ q,
                                              const float* __restrict__ k,
                                              const float* __restrict__ v,
                                              const int* __restrict__ am,
                                              float* __restrict__ out) {
    int qt = blockIdx.x, h = blockIdx.y, b = blockIdx.z;
    int qrow = qt * 128 + threadIdx.x;
    __shared__ float Ks[64][64];
    __shared__ float Vs[64][64];
    __shared__ int   Ms[64];

    float qr[64];
    size_t qbase = ((size_t)(b * L_ + qrow)) * D_ + h * DH_;
    #pragma unroll
    for (int d = 0; d < 64; d++) qr[d] = q[qbase + d] * 0.125f;

    float m = -1e30f, l = 0.0f;
    float acc[64];
    #pragma unroll
    for (int d = 0; d < 64; d++) acc[d] = 0.0f;

    int ntiles = 2 * qt + 2;
    for (int kt = 0; kt < ntiles; kt++) {
        int krow0 = kt * 64;
        {
            int r = threadIdx.x >> 1, half = (threadIdx.x & 1) * 32;
            size_t gb = ((size_t)(b * L_ + krow0 + r)) * D_ + h * DH_ + half;
            float4*       Kd = (float4*)&Ks[r][half];
            const float4* Kg = (const float4*)(k + gb);
            float4*       Vd = (float4*)&Vs[r][half];
            const float4* Vg = (const float4*)(v + gb);
            #pragma unroll
            for (int u = 0; u < 8; u++) { Kd[u] = Kg[u]; Vd[u] = Vg[u]; }
            if (threadIdx.x < 64) Ms[threadIdx.x] = am[b * L_ + krow0 + threadIdx.x];
        }
        __syncthreads();
        int klim = qrow - krow0 + 1;
        if (klim > 64) klim = 64;
        for (int kk = 0; kk < klim; kk++) {
            if (Ms[kk]) {
                float s = 0.0f;
                #pragma unroll
                for (int d = 0; d < 64; d++) s += qr[d] * Ks[kk][d];
                if (s > m) {
                    float c0 = expf(m - s);
                    l *= c0;
                    #pragma unroll
                    for (int d = 0; d < 64; d++) acc[d] *= c0;
                    m = s;
                }
                float p = expf(s - m);
                l += p;
                #pragma unroll
                for (int d = 0; d < 64; d++) acc[d] += p * Vs[kk][d];
            }
        }
        __syncthreads();
    }
    float inv = (l > 0.0f) ? (1.0f / l) : 0.0f;
    #pragma unroll
    for (int d = 0; d < 64; d++) out[qbase + d] = acc[d] * inv;
}

// ---------------- tiled fp32 GEMM (layer path, exact) ----------------
template <int EPI>
__global__ void __launch_bounds__(256) gemm_atw(const float* __restrict__ A,
                                                const float* __restrict__ W,
                                                const float* __restrict__ R,
                                                float* __restrict__ C,
                                                int M, int N, int K) {
    __shared__ float As[16][64];
    __shared__ float Ws[16][64];
    int bm = blockIdx.y * 64, bn = blockIdx.x * 64;
    int tid = threadIdx.x;
    int tx = tid & 15, ty = tid >> 4;
    int lrow = tid >> 2;
    int lk   = (tid & 3) << 2;
    const float* Ap = A + (size_t)(bm + lrow) * K + lk;
    const float* Wp = W + (size_t)(bn + lrow) * K + lk;
    float acc[4][4] = {};
    for (int k0 = 0; k0 < K; k0 += 16) {
        float4 a = *(const float4*)(Ap + k0);
        float4 w = *(const float4*)(Wp + k0);
        As[lk + 0][lrow] = a.x; As[lk + 1][lrow] = a.y;
        As[lk + 2][lrow] = a.z; As[lk + 3][lrow] = a.w;
        Ws[lk + 0][lrow] = w.x; Ws[lk + 1][lrow] = w.y;
        Ws[lk + 2][lrow] = w.z; Ws[lk + 3][lrow] = w.w;
        __syncthreads();
        #pragma unroll
        for (int kk = 0; kk < 16; kk++) {
            float4 av = *(const float4*)&As[kk][ty << 2];
            float4 wv = *(const float4*)&Ws[kk][tx << 2];
            float ar[4] = {av.x, av.y, av.z, av.w};
            float wr[4] = {wv.x, wv.y, wv.z, wv.w};
            #pragma unroll
            for (int i = 0; i < 4; i++)
                #pragma unroll
                for (int j = 0; j < 4; j++) acc[i][j] += ar[i] * wr[j];
        }
        __syncthreads();
    }
    #pragma unroll
    for (int i = 0; i < 4; i++) {
        size_t idx = (size_t)(bm + (ty << 2) + i) * N + bn + (tx << 2);
        float4 vv = make_float4(acc[i][0], acc[i][1], acc[i][2], acc[i][3]);
        if (EPI == 1) {
            float4 rr = *(const float4*)(R + idx);
            vv.x += rr.x; vv.y += rr.y; vv.z += rr.z; vv.w += rr.w;
        }
        if (EPI == 2) {
            vv.x = vv.x / (1.0f + expf(-vv.x));
            vv.y = vv.y / (1.0f + expf(-vv.y));
            vv.z = vv.z / (1.0f + expf(-vv.z));
            vv.w = vv.w / (1.0f + expf(-vv.w));
        }
        *(float4*)(C + idx) = vv;
    }
}

// ---------------- tf32 helpers ----------------
__device__ __forceinline__ unsigned f2tf32(float v) {
    unsigned o;
    asm("cvt.rna.tf32.f32 %0, %1;" : "=r"(o) : "f"(v));
    return o;
}
__device__ __forceinline__ int kperm(int kl) {   // kl in [0,32)
    return (kl & ~7) | ((kl & 3) << 1) | ((kl & 4) >> 2);
}
__device__ __forceinline__ int swz(int row, int col) {
    return row * 32 + (col ^ ((row & 3) << 3));
}
__device__ __forceinline__ uint32_t smem_u32(const void* p) {
    uint32_t a;
    asm("{ .reg .u64 t; cvta.to.shared.u64 t, %1; cvt.u32.u64 %0, t; }" : "=r"(a) : "l"(p));
    return a;
}
#define CP_ASYNC16(dst_u32, src_ptr) \
    asm volatile("cp.async.cg.shared.global [%0], [%1], 16;" :: "r"(dst_u32), "l"(src_ptr))
#define CP_COMMIT() asm volatile("cp.async.commit_group;" ::: "memory")
#define CP_WAIT1()  asm volatile("cp.async.wait_group 1;" ::: "memory")

// fp32 -> tf32-rounded + k-permuted (permutation stays within a 32-elem window)
__global__ void cvt_tf32_perm(const float* __restrict__ x, unsigned* __restrict__ o) {
    int i = blockIdx.x * 256 + threadIdx.x;
    int kl = i & 31;
    o[(i & ~31) | kperm(kl)] = f2tf32(x[i]);
}

// ---------------- tf32 mma.sync GEMM, cp.async double-buffered ----------------
// C[m,n] = sum_k A[m,k]*W[n,k]. Inputs pre-rounded + pre-permuted (g_a32/g_w32).
// 128x128 block, 8 warps (2x4), warp tile 64x32, m16n8k8, BK=32, 2-stage ring.
__global__ void __launch_bounds__(256) lm_tf32(const unsigned* __restrict__ A,
                                               const unsigned* __restrict__ W,
                                               float* __restrict__ C,
                                               int M, int N, int K) {
    extern __shared__ unsigned sbuf[];            // [2][4096] A then [2][4096] W
    unsigned* As[2] = { sbuf,        sbuf + 4096 };
    unsigned* Ws[2] = { sbuf + 8192, sbuf + 12288 };
    const uint32_t sb = smem_u32(sbuf);

    const int bm = blockIdx.y * 128, bn = blockIdx.x * 128;
    const int tid = threadIdx.x;
    const int warp = tid >> 5, lane = tid & 31;
    const int wm = warp >> 2, wn = warp & 3;
    const int gid = lane >> 2, qid = lane & 3;
    const int nchunks = K >> 5;

    // copy geometry: 1024 16B-chunks per matrix per stage; 4 per thread
    // chunk c2 -> row = c2>>3, col4 = (c2&7)*4
    auto issue = [&](int ch, int s) {
        #pragma unroll
        for (int t = 0; t < 4; t++) {
            int c2 = tid + t * 256;
            int row = c2 >> 3, col4 = (c2 & 7) << 2;
            int so = swz(row, col4);
            const unsigned* ga = A + (size_t)(bm + row) * K + ch * 32 + col4;
            const unsigned* gw = W + (size_t)(bn + row) * K + ch * 32 + col4;
            CP_ASYNC16(sb + (uint32_t)(As[s] - sbuf + so) * 4u, ga);
            CP_ASYNC16(sb + (uint32_t)(Ws[s] - sbuf + so) * 4u, gw);
        }
    };

    float cacc[4][4][4];
    #pragma unroll
    for (int i = 0; i < 4; i++)
        #pragma unroll
        for (int j = 0; j < 4; j++)
            #pragma unroll
            for (int f = 0; f < 4; f++) cacc[i][j][f] = 0.0f;

    issue(0, 0); CP_COMMIT();
    if (nchunks > 1) issue(1, 1);
    CP_COMMIT();

    for (int ch = 0; ch < nchunks; ch++) {
        const int s = ch & 1;
        CP_WAIT1();
        __syncthreads();
        const unsigned* Ab = As[s];
        const unsigned* Wb = Ws[s];
        #pragma unroll
        for (int ks = 0; ks < 4; ks++) {
            const int c0 = ks * 8 + 2 * qid;
            unsigned afr[4][4];
            unsigned bfr[4][2];
            #pragma unroll
            for (int mt = 0; mt < 4; mt++) {
                int r0 = wm * 64 + mt * 16 + gid;
                uint2 lo = *(const uint2*)&Ab[swz(r0, c0)];
                uint2 hi = *(const uint2*)&Ab[swz(r0 + 8, c0)];
                afr[mt][0] = lo.x; afr[mt][2] = lo.y;
                afr[mt][1] = hi.x; afr[mt][3] = hi.y;
            }
            #pragma unroll
            for (int nt = 0; nt < 4; nt++) {
                int rn = wn * 32 + nt * 8 + gid;
                uint2 bb = *(const uint2*)&Wb[swz(rn, c0)];
                bfr[nt][0] = bb.x; bfr[nt][1] = bb.y;
            }
            #pragma unroll
            for (int mt = 0; mt < 4; mt++)
                #pragma unroll
                for (int nt = 0; nt < 4; nt++) {
                    asm volatile(
                        "mma.sync.aligned.m16n8k8.row.col.f32.tf32.tf32.f32 "
                        "{%0,%1,%2,%3}, {%4,%5,%6,%7}, {%8,%9}, {%0,%1,%2,%3};\n"
                        : "+f"(cacc[mt][nt][0]), "+f"(cacc[mt][nt][1]),
                          "+f"(cacc[mt][nt][2]), "+f"(cacc[mt][nt][3])
                        : "r"(afr[mt][0]), "r"(afr[mt][1]),
                          "r"(afr[mt][2]), "r"(afr[mt][3]),
                          "r"(bfr[nt][0]), "r"(bfr[nt][1]));
                }
        }
        __syncthreads();
        if (ch + 2 < nchunks) issue(ch + 2, s);
        CP_COMMIT();
    }

    #pragma unroll
    for (int mt = 0; mt < 4; mt++) {
        int row = bm + wm * 64 + mt * 16 + gid;
        #pragma unroll
        for (int nt = 0; nt < 4; nt++) {
            int col = bn + wn * 32 + nt * 8 + qid * 2;
            *(float2*)(C + (size_t)row * N + col) =
                make_float2(cacc[mt][nt][0], cacc[mt][nt][1]);
            *(float2*)(C + (size_t)(row + 8) * N + col) =
                make_float2(cacc[mt][nt][2], cacc[mt][nt][3]);
        }
    }
}

// ---------------- classifier heads on cls token (b, 0) ----------------
__global__ void heads_k(const float* __restrict__ xn,
                        const float* __restrict__ rw, const float* __restrict__ rb,
                        const float* __restrict__ mw, const float* __restrict__ mb,
                        float* __restrict__ out) {
    int b = blockIdx.x;
    int t = threadIdx.x;
    float xv = xn[((size_t)b * L_) * D_ + t];
    float pr = xv * rw[t];
    float pm = xv * mw[t];
    __shared__ float sr[8], sm_[8];
    #pragma unroll
    for (int o = 16; o; o >>= 1) {
        pr += __shfl_xor_sync(0xFFFFFFFFu, pr, o);
        pm += __shfl_xor_sync(0xFFFFFFFFu, pm, o);
    }
    if ((t & 31) == 0) { sr[t >> 5] = pr; sm_[t >> 5] = pm; }
    __syncthreads();
    if (t == 0) {
        float a = 0.0f, c = 0.0f;
        #pragma unroll
        for (int i = 0; i < 8; i++) { a += sr[i]; c += sm_[i]; }
        out[b]      = a + rb[0];
        out[B_ + b] = c + mb[0];
    }
}

// ---------------- driver ----------------
extern "C" void kernel_launch(void* const* d_in, const int* in_sizes, int n_in,
                              void* d_out, int out_size) {
    const int*   token_ids    = (const int*)  d_in[0];
    const int*   token_types  = (const int*)  d_in[1];
    const int*   amask        = (const int*)  d_in[2];
    const float* tok_emb      = (const float*)d_in[3];
    const float* type_emb     = (const float*)d_in[4];
    const float* norm1_w      = (const float*)d_in[5];
    const float* wq           = (const float*)d_in[6];
    const float* wk           = (const float*)d_in[7];
    const float* wv           = (const float*)d_in[8];
    const float* wo           = (const float*)d_in[9];
    const float* norm2_w      = (const float*)d_in[10];
    const float* ff_w1        = (const float*)d_in[11];
    const float* ff_w2        = (const float*)d_in[12];
    const float* final_norm_w = (const float*)d_in[13];
    const float* lm_w         = (const float*)d_in[14];
    const float* read_w       = (const float*)d_in[15];
    const float* read_b       = (const float*)d_in[16];
    const float* mort_w       = (const float*)d_in[17];
    const float* mort_b       = (const float*)d_in[18];
    float* out = (float*)d_out;

    float *x, *xn, *q, *k, *v, *at, *ff;
    unsigned *a32, *w32;
    cudaGetSymbolAddress((void**)&x,   g_x);
    cudaGetSymbolAddress((void**)&xn,  g_xn);
    cudaGetSymbolAddress((void**)&q,   g_q);
    cudaGetSymbolAddress((void**)&k,   g_k);
    cudaGetSymbolAddress((void**)&v,   g_v);
    cudaGetSymbolAddress((void**)&at,  g_at);
    cudaGetSymbolAddress((void**)&ff,  g_ff);
    cudaGetSymbolAddress((void**)&a32, g_a32);
    cudaGetSymbolAddress((void**)&w32, g_w32);

    cudaFuncSetAttribute(lm_tf32, cudaFuncAttributeMaxDynamicSharedMemorySize, 65536);

    embed_k<<<MTOK * D_ / 256, 256>>>(token_ids, token_types, tok_emb, type_emb, x);

    dim3 gqkv(D_ / 64, MTOK / 64);
    dim3 gff1(FF_ / 64, MTOK / 64);
    for (int li = 0; li < NL_; li++) {
        rms_k<<<MTOK, 256>>>(x, norm1_w + li * D_, xn);
        gemm_atw<0><<<gqkv, 256>>>(xn, wq + (size_t)li * D_ * D_, nullptr, q, MTOK, D_, D_);
        gemm_atw<0><<<gqkv, 256>>>(xn, wk + (size_t)li * D_ * D_, nullptr, k, MTOK, D_, D_);
        gemm_atw<0><<<gqkv, 256>>>(xn, wv + (size_t)li * D_ * D_, nullptr, v, MTOK, D_, D_);
        rope_k<<<MTOK * H_ * 32 / 256, 256>>>(q, k);
        attn_k<<<dim3(L_ / 128, H_, B_), 128>>>(q, k, v, amask, at);
        gemm_atw<1><<<gqkv, 256>>>(at, wo + (size_t)li * D_ * D_, x, x, MTOK, D_, D_);
        rms_k<<<MTOK, 256>>>(x, norm2_w + li * D_, xn);
        gemm_atw<2><<<gff1, 256>>>(xn, ff_w1 + (size_t)li * FF_ * D_, nullptr, ff, MTOK, FF_, D_);
        gemm_atw<1><<<gqkv, 256>>>(ff, ff_w2 + (size_t)li * D_ * FF_, x, x, MTOK, D_, FF_);
    }
    rms_k<<<MTOK, 256>>>(x, final_norm_w, xn);
    cvt_tf32_perm<<<MTOK * D_ / 256, 256>>>(xn, a32);
    cvt_tf32_perm<<<V_ * D_ / 256, 256>>>(lm_w, w32);
    lm_tf32<<<dim3(V_ / 128, MTOK / 128), 256, 65536>>>(a32, w32, out, MTOK, V_, D_);
    heads_k<<<B_, 256>>>(xn, read_w, read_b, mort_w, mort_b, out + (size_t)MTOK * V_);
}